// round 7
// baseline (speedup 1.0000x reference)
#include <cuda_runtime.h>

#define NN 4
#define C  64
#define H  160
#define W  320
#define DISP 48
#define G  8
#define HW (H*W)
#define ROWB 32                        // 8 floats per w position (one group)
#define ROW_BYTES (W * ROWB)           // 10KB per h-row buffer

// XOR swizzle, 16B chunks, 32B rows. Compute/staging lanes step w by 4
// (addr step 128B): chunk (w>>2)&7 steps 1 per lane -> 8 distinct 16B chunks
// per 8-lane phase -> conflict-free. Bijective (bits[4:7) ^= bits[7:10)).
__device__ __forceinline__ unsigned sw_off(int w, int colbyte) {
    unsigned off = (unsigned)(w * ROWB + colbyte);
    off ^= (((unsigned)w >> 2) & 7u) << 4;
    return off;
}

// dot of output j with ring slot s; two independent 4-chains + add.
#define DOT(j, s)                                                             \
    ((lw[0][j]*ra[s].x + lw[1][j]*ra[s].y + lw[2][j]*ra[s].z + lw[3][j]*ra[s].w) + \
     (lw[4][j]*rb[s].x + lw[5][j]*rb[s].y + lw[6][j]*rb[s].z + lw[7][j]*rb[s].w))

__global__ __launch_bounds__(160, 5)
void gwc_kernel(const float* __restrict__ lg,
                const float* __restrict__ rg,
                float* __restrict__ out) {
    __shared__ __align__(16) char rS[2 * ROW_BYTES];

    const int hp  = blockIdx.x;          // h pair 0..79
    const int n   = blockIdx.y;
    const int g   = blockIdx.z;
    const int tid = threadIdx.x;
    const int hh  = tid / 80;            // local row 0/1
    const int h   = hp * 2 + hh;
    const int w0  = (tid % 80) * 4;      // this thread's 4 output columns

    char* buf = rS + hh * ROW_BYTES;

    // ---- l channels: 8 contiguous LDG.128 (w0 = 4*lane -> coalesced) ----
    const float* lp = lg + ((n * C + g * 8) * H + h) * W + w0;
    float lw[8][4];
    #pragma unroll
    for (int c = 0; c < 8; ++c) {
        float4 t = *(const float4*)(lp + c * HW);
        lw[c][0] = t.x; lw[c][1] = t.y; lw[c][2] = t.z; lw[c][3] = t.w;
    }

    // ---- Stage own row's 8 r channels: LDG.128 + 4 conflict-free STS.32 ----
    {
        const float* rbase = rg + ((n * C + g * 8) * H + h) * W + w0;
        #pragma unroll
        for (int c = 0; c < 8; ++c) {
            float4 t = *(const float4*)(rbase + c * HW);
            *(float*)(buf + sw_off(w0 + 0, c * 4)) = t.x;
            *(float*)(buf + sw_off(w0 + 1, c * 4)) = t.y;
            *(float*)(buf + sw_off(w0 + 2, c * 4)) = t.z;
            *(float*)(buf + sw_off(w0 + 3, c * 4)) = t.w;
        }
    }
    __syncthreads();

    // ---- Compute: 4-slot ring over disparity (slot = w index & 3) ----
    float4 ra[4], rb[4];
    #pragma unroll
    for (int j = 0; j < 4; ++j) {
        ra[j] = *(const float4*)(buf + sw_off(w0 + j, 0));
        rb[j] = *(const float4*)(buf + sw_off(w0 + j, 16));
    }

    float* op = out + (((n * G + g) * DISP) * H + h) * W + w0;

    if (w0 >= DISP) {
        // Fast path (no boundary): unconditional ring refill, no predicates.
        #pragma unroll 4
        for (int d = 0; d < DISP; ++d) {
            const int e  = d & 3;
            const int sn = (4 - e) & 3;          // slot of new position w0-d
            if (d > 0) {
                const int wn = w0 - d;
                ra[sn] = *(const float4*)(buf + sw_off(wn, 0));
                rb[sn] = *(const float4*)(buf + sw_off(wn, 16));
            }
            float4 o;
            o.x = DOT(0, (0 - e) & 3) * 0.125f;
            o.y = DOT(1, (1 - e) & 3) * 0.125f;
            o.z = DOT(2, (2 - e) & 3) * 0.125f;
            o.w = DOT(3, (3 - e) & 3) * 0.125f;
            __stcs((float4*)(op + d * HW), o);
        }
    } else {
        #pragma unroll 4
        for (int d = 0; d < DISP; ++d) {
            const int e  = d & 3;
            const int sn = (4 - e) & 3;
            const int wn = w0 - d;
            if (d > 0 && wn >= 0) {
                ra[sn] = *(const float4*)(buf + sw_off(wn, 0));
                rb[sn] = *(const float4*)(buf + sw_off(wn, 16));
            }
            float4 o;
            o.x = (w0 + 0 >= d) ? DOT(0, (0 - e) & 3) * 0.125f : 1.0f;
            o.y = (w0 + 1 >= d) ? DOT(1, (1 - e) & 3) * 0.125f : 1.0f;
            o.z = (w0 + 2 >= d) ? DOT(2, (2 - e) & 3) * 0.125f : 1.0f;
            o.w = (w0 + 3 >= d) ? DOT(3, (3 - e) & 3) * 0.125f : 1.0f;
            __stcs((float4*)(op + d * HW), o);
        }
    }
}

extern "C" void kernel_launch(void* const* d_in, const int* in_sizes, int n_in,
                              void* d_out, int out_size) {
    const float* l = (const float*)d_in[0];
    const float* r = (const float*)d_in[1];
    float* out = (float*)d_out;

    dim3 grid(H / 2, NN, G);             // 2560 CTAs: (h-pair, n, group)
    gwc_kernel<<<grid, 160>>>(l, r, out);
}

// round 8
// speedup vs baseline: 1.5452x; 1.5452x over previous
#include <cuda_runtime.h>

#define NN 4
#define C  64
#define H  160
#define W  320
#define DISP 48
#define G  8
#define HW (H*W)
#define ROWB 32                        // 8 floats per w position (one group)
#define SMEM_BYTES (W * ROWB)          // 10KB

// XOR swizzle, 16B chunks, 32B rows.
// Compute lanes step w by 4 (addr step 128B): chunk = (w>>2)&7 steps 1/lane
// -> 8 distinct 16B chunks per 8-lane LDS.128 phase -> conflict-free.
// Staging lanes step w by 1: chunk = ((w&3)<<1 | cbit) ^ ((w>>2)&7) walks
// {0,2,4,6,1,3,5,7} over 8 lanes -> conflict-free STS.128 too.
__device__ __forceinline__ unsigned sw_off(int w, int colbyte) {
    unsigned off = (unsigned)(w * ROWB + colbyte);
    off ^= (((unsigned)w >> 2) & 7u) << 4;
    return off;
}

// dot of output j with ring slot s; two independent 4-chains + add.
#define DOT(j, s)                                                             \
    ((lw[0][j]*ra[s].x + lw[1][j]*ra[s].y + lw[2][j]*ra[s].z + lw[3][j]*ra[s].w) + \
     (lw[4][j]*rb[s].x + lw[5][j]*rb[s].y + lw[6][j]*rb[s].z + lw[7][j]*rb[s].w))

__global__ __launch_bounds__(80, 8)
void gwc_kernel(const float* __restrict__ lg,
                const float* __restrict__ rg,
                float* __restrict__ out) {
    __shared__ __align__(16) char rS[SMEM_BYTES];

    const int h   = blockIdx.x;
    const int n   = blockIdx.y;
    const int g   = blockIdx.z;
    const int tid = threadIdx.x;
    const int w0  = tid * 4;             // this thread's 4 output columns

    // ---- l channels: 8 contiguous LDG.128, issued before staging ----
    const float* lp = lg + ((n * C + g * 8) * H + h) * W + w0;
    float lw[8][4];
    #pragma unroll
    for (int c = 0; c < 8; ++c) {
        float4 t = *(const float4*)(lp + c * HW);
        lw[c][0] = t.x; lw[c][1] = t.y; lw[c][2] = t.z; lw[c][3] = t.w;
    }

    // ---- Stage 8 r channels, transposed [w][c], swizzled ----
    // 640 float4 items, 8 per thread: gather 4 coalesced scalar LDG + STS.128.
    {
        const float* rbase = rg + ((n * C + g * 8) * H + h) * W;
        #pragma unroll
        for (int k = 0; k < 8; ++k) {
            int i  = tid + k * 80;
            int w  = i % W;
            int c4 = (i / W) * 4;        // 0 or 4
            int gb = c4 * HW + w;
            float4 rv;
            rv.x = rbase[gb];
            rv.y = rbase[gb + HW];
            rv.z = rbase[gb + 2 * HW];
            rv.w = rbase[gb + 3 * HW];
            *(float4*)(rS + sw_off(w, c4 * 4)) = rv;
        }
    }
    __syncthreads();

    // ---- Compute: 4-slot ring over disparity (slot = w index & 3) ----
    float4 ra[4], rb[4];
    #pragma unroll
    for (int j = 0; j < 4; ++j) {
        ra[j] = *(const float4*)(rS + sw_off(w0 + j, 0));
        rb[j] = *(const float4*)(rS + sw_off(w0 + j, 16));
    }

    float* op = out + (((n * G + g) * DISP) * H + h) * W + w0;

    if (w0 >= DISP) {
        // Fast path (tid >= 12): unconditional ring refill, no predicates.
        #pragma unroll 4
        for (int d = 0; d < DISP; ++d) {
            const int e  = d & 3;
            const int sn = (4 - e) & 3;          // slot of new position w0-d
            if (d > 0) {
                const int wn = w0 - d;
                ra[sn] = *(const float4*)(rS + sw_off(wn, 0));
                rb[sn] = *(const float4*)(rS + sw_off(wn, 16));
            }
            float4 o;
            o.x = DOT(0, (0 - e) & 3) * 0.125f;
            o.y = DOT(1, (1 - e) & 3) * 0.125f;
            o.z = DOT(2, (2 - e) & 3) * 0.125f;
            o.w = DOT(3, (3 - e) & 3) * 0.125f;
            __stcs((float4*)(op + d * HW), o);
        }
    } else {
        #pragma unroll 4
        for (int d = 0; d < DISP; ++d) {
            const int e  = d & 3;
            const int sn = (4 - e) & 3;
            const int wn = w0 - d;
            if (d > 0 && wn >= 0) {
                ra[sn] = *(const float4*)(rS + sw_off(wn, 0));
                rb[sn] = *(const float4*)(rS + sw_off(wn, 16));
            }
            float4 o;
            o.x = (w0 + 0 >= d) ? DOT(0, (0 - e) & 3) * 0.125f : 1.0f;
            o.y = (w0 + 1 >= d) ? DOT(1, (1 - e) & 3) * 0.125f : 1.0f;
            o.z = (w0 + 2 >= d) ? DOT(2, (2 - e) & 3) * 0.125f : 1.0f;
            o.w = (w0 + 3 >= d) ? DOT(3, (3 - e) & 3) * 0.125f : 1.0f;
            __stcs((float4*)(op + d * HW), o);
        }
    }
}

extern "C" void kernel_launch(void* const* d_in, const int* in_sizes, int n_in,
                              void* d_out, int out_size) {
    const float* l = (const float*)d_in[0];
    const float* r = (const float*)d_in[1];
    float* out = (float*)d_out;

    dim3 grid(H, NN, G);                 // 5120 CTAs: (h, n, group)
    gwc_kernel<<<grid, 80>>>(l, r, out);
}